// round 14
// baseline (speedup 1.0000x reference)
#include <cuda_runtime.h>
#include <cuda_fp16.h>
#include <cstdint>
#include <cstddef>

// Problem constants (fixed by the reference)
#define N_NODES 50000
#define N_EDGES 312500
#define SCAN_BLOCKS 196         // 196 * 256 = 50176 >= N_NODES; co-resident on 148 SMs

// ---------------- scratch (static device globals; no allocation) ----------------
__device__ __align__(16) __half g_x  [(size_t)N_NODES * 256];
__device__ __align__(16) __half g_tx1[(size_t)N_NODES * 256];
__device__ __align__(16) __half g_tx2[(size_t)N_NODES * 256];
__device__ __align__(16) __half g_h  [(size_t)N_NODES * 256];
__device__ __align__(16) __half g_p  [(size_t)N_NODES * 128];
__device__ __align__(16) __half g_w1t[256 * 768];   // W1^T [n][k]
__device__ __align__(16) __half g_w2t[256 * 512];   // fused layer-2 B^T [n][k]
__device__ float g_deg[N_NODES];
__device__ int   g_cnt[N_NODES];
__device__ int   g_fill[N_NODES];
__device__ int   g_rowptr[N_NODES + 1];
__device__ int   g_dst[N_EDGES];
__device__ float g_w[N_EDGES];
__device__ int   g_is64;
__device__ int   g_bsum[256];
__device__ int   g_boff[256];
__device__ int   g_scan_ctr;
__device__ int   g_scan_done;
__device__ int   g_scan_ctr2;
__device__ int   g_scan_done2;

// Buffer ids: 1 = tx1, 2 = tx2, 3 = h, 4 = x, 5 = p.
template <int ID>
__device__ __forceinline__ const __half* hbuf() {
    if (ID == 1) return g_tx1;
    if (ID == 2) return g_tx2;
    if (ID == 3) return g_h;
    if (ID == 4) return g_x;
    return g_p;
}
template <int ID>
__device__ __forceinline__ __half* hbuf_w() {
    if (ID == 1) return g_tx1;
    if (ID == 2) return g_tx2;
    if (ID == 3) return g_h;
    if (ID == 4) return g_x;
    return g_p;
}

// ---------------- cp.async ----------------
__device__ __forceinline__ void cpasync16(uint32_t dst, const void* src, int srcsize) {
    asm volatile("cp.async.ca.shared.global [%0], [%1], 16, %2;\n"
                 :: "r"(dst), "l"(src), "r"(srcsize));
}
__device__ __forceinline__ void cp_commit() {
    asm volatile("cp.async.commit_group;\n" ::: "memory");
}
__device__ __forceinline__ void cp_wait2() {
    asm volatile("cp.async.wait_group 2;\n" ::: "memory");
}
__device__ __forceinline__ void cp_wait1() {
    asm volatile("cp.async.wait_group 1;\n" ::: "memory");
}
__device__ __forceinline__ void cp_wait0() {
    asm volatile("cp.async.wait_group 0;\n" ::: "memory");
}

// ---------------- fp16 mma + ldmatrix ----------------
__device__ __forceinline__ void mma_f16(float c[4], const uint32_t a[4],
                                        const uint32_t b[2]) {
    asm volatile(
        "mma.sync.aligned.m16n8k16.row.col.f32.f16.f16.f32 "
        "{%0,%1,%2,%3}, {%4,%5,%6,%7}, {%8,%9}, {%0,%1,%2,%3};\n"
        : "+f"(c[0]), "+f"(c[1]), "+f"(c[2]), "+f"(c[3])
        : "r"(a[0]), "r"(a[1]), "r"(a[2]), "r"(a[3]), "r"(b[0]), "r"(b[1]));
}

__device__ __forceinline__ void ldsm_x4(uint32_t& r0, uint32_t& r1,
                                        uint32_t& r2, uint32_t& r3,
                                        uint32_t saddr) {
    asm volatile("ldmatrix.sync.aligned.m8n8.x4.shared.b16 {%0,%1,%2,%3}, [%4];"
                 : "=r"(r0), "=r"(r1), "=r"(r2), "=r"(r3) : "r"(saddr));
}

// ---------------- edge-index accessors ----------------
__device__ __forceinline__ int edge_row(const int* ei, int e) {
    return g_is64 ? ei[2 * e] : ei[e];
}
__device__ __forceinline__ int edge_col(const int* ei, int e) {
    return g_is64 ? ei[2 * (N_EDGES + e)] : ei[N_EDGES + e];
}

// ---------------- merged init: zero counters + dtype detect + scan flags ----------------
__global__ void init_kernel(const int* __restrict__ ei) {
    int i = blockIdx.x * 256 + threadIdx.x;
    if (i < N_NODES) {
        g_deg[i] = 0.f;
        g_cnt[i] = 0;
        g_fill[i] = 0;
    }
    if (blockIdx.x == 1 && threadIdx.x == 0) {
        g_scan_ctr = 0;
        g_scan_done = 0;
        g_scan_ctr2 = 0;
        g_scan_done2 = 0;
    }
    if (blockIdx.x == 0) {
        __shared__ int any_nonzero;
        if (threadIdx.x == 0) any_nonzero = 0;
        __syncthreads();
        for (int j = threadIdx.x; j < 2048; j += 256) {
            if (ei[2 * j + 1] != 0) { any_nonzero = 1; break; }
        }
        __syncthreads();
        if (threadIdx.x == 0) g_is64 = (any_nonzero == 0) ? 1 : 0;
    }
}

// ---------------- merged prep: conv_x + deg_count + weight prep ----------------
__global__ void prep_kernel(const int* __restrict__ ei,
                            const float* __restrict__ ew,
                            const float* __restrict__ x,
                            const float* __restrict__ W1,
                            const float* __restrict__ W2) {
    int i = blockIdx.x * 256 + threadIdx.x;

    // Task 1: x -> half (uint2 = 4 halfs each; N_NODES*64 items)
    if (i < N_NODES * 64) {
        float4 v = ((const float4*)x)[i];
        __half2 h0 = __floats2half2_rn(v.x, v.y);
        __half2 h1 = __floats2half2_rn(v.z, v.w);
        uint2 o;
        o.x = *(uint32_t*)&h0;
        o.y = *(uint32_t*)&h1;
        ((uint2*)g_x)[i] = o;
    }
    // Task 2: degree + count
    if (i < N_EDGES) {
        int r = edge_row(ei, i);
        atomicAdd(&g_deg[r], ew[i]);
        atomicAdd(&g_cnt[r], 1);
    }
    // Task 3: weight transpose/fold to half (2x folded into W2_2 for P path)
    if (i < 256 * 768) {
        int n = i / 768, k = i % 768;
        g_w1t[i] = __float2half_rn(W1[k * 256 + n]);
    } else if (i < 256 * 768 + 256 * 512) {
        int j = i - 256 * 768;
        int n = j / 512, k = j % 512;
        float v;
        if (n < 128) {
            v = (k < 256) ? (W2[k * 128 + n] - W2[65536 + k * 128 + n])
                          : W2[32768 + (k - 256) * 128 + n];
        } else {
            v = (k < 256) ? 0.f : 2.f * W2[65536 + (k - 256) * 128 + (n - 128)];
        }
        g_w2t[j] = __float2half_rn(v);
    }
}

// ---------------- fused scan + CSR build (two ticket barriers) ----------------
// Safe: all 196 blocks (256 thr) are co-resident on 148 SMs.
__global__ void scan_build_kernel(const int* __restrict__ ei,
                                  const float* __restrict__ ew) {
    __shared__ int s[256];
    __shared__ int is_last;
    __shared__ int blockoff;
    int t = threadIdx.x;
    int b = blockIdx.x;
    int i = b * 256 + t;
    int v = (i < N_NODES) ? g_cnt[i] : 0;

    // ---- phase 1: local inclusive scan ----
    s[t] = v;
    __syncthreads();
    for (int off = 1; off < 256; off <<= 1) {
        int u = (t >= off) ? s[t - off] : 0;
        __syncthreads();
        s[t] += u;
        __syncthreads();
    }
    int local_incl = s[t];
    int block_sum = s[255];
    __syncthreads();

    if (t == 0) {
        g_bsum[b] = block_sum;
        __threadfence();
        int ticket = atomicAdd(&g_scan_ctr, 1);
        is_last = (ticket == SCAN_BLOCKS - 1) ? 1 : 0;
    }
    __syncthreads();

    if (is_last) {
        int vv = (t < SCAN_BLOCKS) ? atomicAdd(&g_bsum[t], 0) : 0;
        s[t] = vv;
        __syncthreads();
        for (int off = 1; off < 256; off <<= 1) {
            int u = (t >= off) ? s[t - off] : 0;
            __syncthreads();
            s[t] += u;
            __syncthreads();
        }
        if (t < SCAN_BLOCKS) g_boff[t] = s[t] - vv;   // exclusive
        if (t == 255) g_rowptr[N_NODES] = s[255];
        __threadfence();
        if (t == 0) atomicExch(&g_scan_done, 1);
    }

    if (t == 0) {
        while (atomicAdd(&g_scan_done, 0) == 0) { }
        blockoff = atomicAdd(&g_boff[b], 0);
    }
    __syncthreads();
    if (i < N_NODES) g_rowptr[i] = blockoff + local_incl - v;  // exclusive

    // ---- phase 2 barrier: all rowptr entries visible ----
    if (t == 0) {
        __threadfence();
        int ticket = atomicAdd(&g_scan_ctr2, 1);
        if (ticket == SCAN_BLOCKS - 1) atomicExch(&g_scan_done2, 1);
        while (atomicAdd(&g_scan_done2, 0) == 0) { }
    }
    __syncthreads();

    // ---- phase 3: CSR fill (stride loop over edges) ----
    for (int e = b * 256 + t; e < N_EDGES; e += SCAN_BLOCKS * 256) {
        int r = edge_row(ei, e);
        int c = edge_col(ei, e);
        float dr = g_deg[r], dc = g_deg[c];
        float ir = dr > 0.f ? rsqrtf(dr) : 0.f;
        float ic = dc > 0.f ? rsqrtf(dc) : 0.f;
        float w = -ir * ew[e] * ic;
        int pos = atomicAdd(&g_fill[r], 1);
        int idx = g_rowptr[r] + pos;
        g_dst[idx] = c;
        g_w[idx] = w;
    }
}

// ---------------- fp16 SpMM (256-wide, 2-edge unroll; known-good) ----------------
__device__ __forceinline__ void acc8(float* a, uint4 u, float w) {
    float2 f;
    f = __half22float2(*(__half2*)&u.x); a[0] += w * f.x; a[1] += w * f.y;
    f = __half22float2(*(__half2*)&u.y); a[2] += w * f.x; a[3] += w * f.y;
    f = __half22float2(*(__half2*)&u.z); a[4] += w * f.x; a[5] += w * f.y;
    f = __half22float2(*(__half2*)&u.w); a[6] += w * f.x; a[7] += w * f.y;
}

template <int SRC, int SUB, int DST>
__global__ __launch_bounds__(256)
void spmm256_kernel(float alpha, float beta) {
    const __half* src = hbuf<SRC>();
    __half*       dst = hbuf_w<DST>();

    int warp = (blockIdx.x * blockDim.x + threadIdx.x) >> 5;
    int lane = threadIdx.x & 31;
    if (warp >= N_NODES) return;
    int s = g_rowptr[warp];
    int e = g_rowptr[warp + 1];

    float aA[8] = {0, 0, 0, 0, 0, 0, 0, 0};
    float aB[8] = {0, 0, 0, 0, 0, 0, 0, 0};

    int i = s;
    for (; i + 2 <= e; i += 2) {
        float w0 = g_w[i], w1 = g_w[i + 1];
        uint4 u0 = ((const uint4*)(src + (size_t)g_dst[i] * 256))[lane];
        uint4 u1 = ((const uint4*)(src + (size_t)g_dst[i + 1] * 256))[lane];
        acc8(aA, u0, w0);
        acc8(aB, u1, w1);
    }
    if (i < e) {
        uint4 u0 = ((const uint4*)(src + (size_t)g_dst[i] * 256))[lane];
        acc8(aA, u0, g_w[i]);
    }
    float a[8];
#pragma unroll
    for (int j = 0; j < 8; j++) a[j] = aA[j] + aB[j];

    if (SUB >= 0) {
        const __half* sub = hbuf<(SUB >= 0 ? SUB : 1)>();
        uint4 su = ((const uint4*)(sub + (size_t)warp * 256))[lane];
        float sv[8];
        float2 f;
        f = __half22float2(*(__half2*)&su.x); sv[0] = f.x; sv[1] = f.y;
        f = __half22float2(*(__half2*)&su.y); sv[2] = f.x; sv[3] = f.y;
        f = __half22float2(*(__half2*)&su.z); sv[4] = f.x; sv[5] = f.y;
        f = __half22float2(*(__half2*)&su.w); sv[6] = f.x; sv[7] = f.y;
#pragma unroll
        for (int j = 0; j < 8; j++) a[j] = alpha * a[j] + beta * sv[j];
    }

    uint4 o;
    __half2 h;
    h = __floats2half2_rn(a[0], a[1]); o.x = *(uint32_t*)&h;
    h = __floats2half2_rn(a[2], a[3]); o.y = *(uint32_t*)&h;
    h = __floats2half2_rn(a[4], a[5]); o.z = *(uint32_t*)&h;
    h = __floats2half2_rn(a[6], a[7]); o.w = *(uint32_t*)&h;
    ((uint4*)(dst + (size_t)warp * 256))[lane] = o;
}

// ---------------- final SpMM: out(f32) += L @ P (2x pre-folded into P) ----------------
__global__ __launch_bounds__(256)
void spmm_out_kernel(float* __restrict__ out) {
    int warp = (blockIdx.x * blockDim.x + threadIdx.x) >> 5;
    int lane = threadIdx.x & 31;
    if (warp >= N_NODES) return;
    int s = g_rowptr[warp];
    int e = g_rowptr[warp + 1];

    float aA[4] = {0, 0, 0, 0};
    float aB[4] = {0, 0, 0, 0};
    int i = s;
    for (; i + 2 <= e; i += 2) {
        float w0 = g_w[i], w1 = g_w[i + 1];
        uint2 u0 = ((const uint2*)(g_p + (size_t)g_dst[i] * 128))[lane];
        uint2 u1 = ((const uint2*)(g_p + (size_t)g_dst[i + 1] * 128))[lane];
        float2 f;
        f = __half22float2(*(__half2*)&u0.x); aA[0] += w0 * f.x; aA[1] += w0 * f.y;
        f = __half22float2(*(__half2*)&u0.y); aA[2] += w0 * f.x; aA[3] += w0 * f.y;
        f = __half22float2(*(__half2*)&u1.x); aB[0] += w1 * f.x; aB[1] += w1 * f.y;
        f = __half22float2(*(__half2*)&u1.y); aB[2] += w1 * f.x; aB[3] += w1 * f.y;
    }
    if (i < e) {
        float w0 = g_w[i];
        uint2 u0 = ((const uint2*)(g_p + (size_t)g_dst[i] * 128))[lane];
        float2 f;
        f = __half22float2(*(__half2*)&u0.x); aA[0] += w0 * f.x; aA[1] += w0 * f.y;
        f = __half22float2(*(__half2*)&u0.y); aA[2] += w0 * f.x; aA[3] += w0 * f.y;
    }
    float4* op = (float4*)(out + (size_t)warp * 128) + lane;
    float4 o = *op;
    o.x += aA[0] + aB[0];
    o.y += aA[1] + aB[1];
    o.z += aA[2] + aB[2];
    o.w += aA[3] + aB[3];
    *op = o;
}

// ---------------- fp16 mma GEMM: 3-stage cp.async pipeline + ldmatrix ----------------
// Block 128(M) x 128(N), 256 threads, 8 warps (4m x 2n), warp tile 32x64,
// BK = 32 halfs, mma.m16n8k16. Dynamic smem: 3 x (A 128x40 + B 128x40) halfs = 60KB.
// LAYER 1: A=[x|tx1|tx2] (K=768), B=g_w1t, out=h (half, bias+relu).
// LAYER 2: A=[h|Z=tx1] (K=512), B=g_w2t, col<128 -> out(f32,+b2),
//          col>=128 -> P (half, weights pre-scaled by 2); those blocks skip
//          stages 0-7 (zero weights for k<256).

#define GEMM_SMEM_BYTES (3 * 2 * 128 * 40 * 2)   // 61440

template <int LAYER>
__global__ __launch_bounds__(256, 2)
void gemm_h(const float* __restrict__ bias, float* __restrict__ ext_out) {
    const int K  = (LAYER == 1) ? 768 : 512;
    const int NS = K / 32;

    extern __shared__ __half dsm[];
    __half* Asm = dsm;                  // 3 bufs x 5120 halfs
    __half* Bsm = dsm + 3 * 5120;       // 3 bufs x 5120 halfs

    const int tid  = threadIdx.x;
    const int lane = tid & 31;
    const int wid  = tid >> 5;
    const int g = lane >> 2;
    const int t = lane & 3;

    const int bm = blockIdx.y * 128;
    const int bn = blockIdx.x * 128;
    const int wm = (wid & 3) * 32;
    const int wn = (wid >> 2) * 64;

    const uint32_t s_as = (uint32_t)__cvta_generic_to_shared(Asm);
    const uint32_t s_bs = (uint32_t)__cvta_generic_to_shared(Bsm);

    // ldmatrix lane addressing
    const int lsub = lane >> 3;
    const int lrow = lane & 7;
    const int a_off0 = (wm + lrow + ((lsub & 1) ? 8 : 0)) * 40 + ((lsub & 2) ? 8 : 0);
    const int b_off0 = (wn + lrow + ((lsub & 2) ? 8 : 0)) * 40 + ((lsub & 1) ? 8 : 0);

    const int s0 = (LAYER == 2 && bn >= 128) ? 8 : 0;

    float acc[2][8][4];
#pragma unroll
    for (int i = 0; i < 2; i++)
#pragma unroll
        for (int j = 0; j < 8; j++)
#pragma unroll
            for (int q = 0; q < 4; q++) acc[i][j][q] = 0.f;

    const int st_row = tid >> 2;        // 0..63 (x2 passes -> 128)
    const int st_c   = (tid & 3) * 8;   // 0,8,16,24

    auto issue = [&](int s) {
        const int buf = s % 3;
        const __half* seg;
        if (LAYER == 1) seg = (s < 8) ? g_x : ((s < 16) ? g_tx1 : g_tx2);
        else            seg = (s < 8) ? g_h : g_tx1;
        const __half* Bt = (LAYER == 1) ? g_w1t : g_w2t;
        const int kb = (s & 7) * 32;
#pragma unroll
        for (int p = 0; p < 2; p++) {
            int row = p * 64 + st_row;
            int rg = bm + row;
            int ok = (rg < N_NODES) ? 16 : 0;
            const __half* src = seg + (size_t)(ok ? rg : 0) * 256 + kb + st_c;
            cpasync16(s_as + (uint32_t)(buf * 5120 + row * 40 + st_c) * 2, src, ok);
        }
#pragma unroll
        for (int p = 0; p < 2; p++) {
            int n = p * 64 + st_row;
            const __half* src = Bt + (size_t)(bn + n) * K + s * 32 + st_c;
            cpasync16(s_bs + (uint32_t)(buf * 5120 + n * 40 + st_c) * 2, src, 16);
        }
        cp_commit();
    };

    issue(s0);
    issue(s0 + 1);
    issue(s0 + 2);

    for (int s = s0; s < NS; s++) {
        if (NS - 1 - s >= 2)      cp_wait2();
        else if (NS - 1 - s == 1) cp_wait1();
        else                      cp_wait0();
        __syncthreads();
        const int buf = s % 3;
        const uint32_t abase = s_as + (uint32_t)(buf * 5120) * 2;
        const uint32_t bbase = s_bs + (uint32_t)(buf * 5120) * 2;
#pragma unroll
        for (int ks = 0; ks < 2; ks++) {
            const int k0 = ks * 16;
            uint32_t a[2][4];
            uint32_t b[8][2];
#pragma unroll
            for (int i = 0; i < 2; i++)
                ldsm_x4(a[i][0], a[i][1], a[i][2], a[i][3],
                        abase + (uint32_t)(a_off0 + i * 16 * 40 + k0) * 2);
#pragma unroll
            for (int jp = 0; jp < 4; jp++)
                ldsm_x4(b[2 * jp][0], b[2 * jp][1], b[2 * jp + 1][0], b[2 * jp + 1][1],
                        bbase + (uint32_t)(b_off0 + jp * 16 * 40 + k0) * 2);
#pragma unroll
            for (int i = 0; i < 2; i++)
#pragma unroll
                for (int j = 0; j < 8; j++)
                    mma_f16(acc[i][j], a[i], b[j]);
        }
        __syncthreads();
        if (s + 3 < NS) issue(s + 3);
    }

    // ---- epilogue ----
#pragma unroll
    for (int i = 0; i < 2; i++) {
        int r0 = bm + wm + 16 * i + g;
        int r1 = r0 + 8;
#pragma unroll
        for (int j = 0; j < 8; j++) {
            int col = bn + wn + 8 * j + 2 * t;
            float v0 = acc[i][j][0], v1 = acc[i][j][1];
            float v2 = acc[i][j][2], v3 = acc[i][j][3];
            if (LAYER == 1) {
                float bb0 = bias[col], bb1 = bias[col + 1];
                v0 = fmaxf(v0 + bb0, 0.f); v1 = fmaxf(v1 + bb1, 0.f);
                v2 = fmaxf(v2 + bb0, 0.f); v3 = fmaxf(v3 + bb1, 0.f);
                __half2 h01 = __floats2half2_rn(v0, v1);
                __half2 h23 = __floats2half2_rn(v2, v3);
                if (r0 < N_NODES) *(uint32_t*)(g_h + (size_t)r0 * 256 + col) = *(uint32_t*)&h01;
                if (r1 < N_NODES) *(uint32_t*)(g_h + (size_t)r1 * 256 + col) = *(uint32_t*)&h23;
            } else {
                if (col < 128) {
                    float bb0 = bias[col], bb1 = bias[col + 1];
                    if (r0 < N_NODES)
                        *(float2*)(ext_out + (size_t)r0 * 128 + col) = make_float2(v0 + bb0, v1 + bb1);
                    if (r1 < N_NODES)
                        *(float2*)(ext_out + (size_t)r1 * 128 + col) = make_float2(v2 + bb0, v3 + bb1);
                } else {
                    int pc = col - 128;
                    __half2 h01 = __floats2half2_rn(v0, v1);
                    __half2 h23 = __floats2half2_rn(v2, v3);
                    if (r0 < N_NODES) *(uint32_t*)(g_p + (size_t)r0 * 128 + pc) = *(uint32_t*)&h01;
                    if (r1 < N_NODES) *(uint32_t*)(g_p + (size_t)r1 * 128 + pc) = *(uint32_t*)&h23;
                }
            }
        }
    }
}

// ---------------- launch ----------------

extern "C" void kernel_launch(void* const* d_in, const int* in_sizes, int n_in,
                              void* d_out, int out_size) {
    const float* x  = (const float*)d_in[0];
    const int*   ei = (const int*)d_in[1];
    const float* ew = (const float*)d_in[2];
    const float* W1 = (const float*)d_in[3];   // [3,256,256]
    const float* b1 = (const float*)d_in[4];
    const float* W2 = (const float*)d_in[5];   // [3,256,128]
    const float* b2 = (const float*)d_in[6];
    float*       out = (float*)d_out;

    // dynamic smem opt-in (host-side attribute set; idempotent)
    cudaFuncSetAttribute(gemm_h<1>, cudaFuncAttributeMaxDynamicSharedMemorySize, GEMM_SMEM_BYTES);
    cudaFuncSetAttribute(gemm_h<2>, cudaFuncAttributeMaxDynamicSharedMemorySize, GEMM_SMEM_BYTES);

    // CSR build + conversions (3 prelude launches)
    init_kernel<<<SCAN_BLOCKS, 256>>>(ei);
    prep_kernel<<<(N_NODES * 64 + 255) / 256, 256>>>(ei, ew, x, W1, W2);
    scan_build_kernel<<<SCAN_BLOCKS, 256>>>(ei, ew);

    const int spmm_blocks = (N_NODES * 32 + 255) / 256;
    const dim3 ggrid(2, (N_NODES + 127) / 128);   // N=256 for both layers

    // ---- layer 1 ----
    spmm256_kernel<4, -1, 1><<<spmm_blocks, 256>>>(1.f, 0.f);        // tx1 = L @ x
    spmm256_kernel<1, 4, 2><<<spmm_blocks, 256>>>(2.f, -1.f);        // tx2 = 2 L tx1 - x
    gemm_h<1><<<ggrid, 256, GEMM_SMEM_BYTES>>>(b1, nullptr);         // h

    // ---- layer 2 (commuted + fused) ----
    spmm256_kernel<3, -1, 1><<<spmm_blocks, 256>>>(1.f, 0.f);        // Z = L @ h -> tx1
    gemm_h<2><<<ggrid, 256, GEMM_SMEM_BYTES>>>(b2, out);             // [out_partial | P]
    spmm_out_kernel<<<spmm_blocks, 256>>>(out);                      // out += L @ P

    (void)in_sizes; (void)n_in; (void)out_size;
}

// round 15
// speedup vs baseline: 1.0204x; 1.0204x over previous
#include <cuda_runtime.h>
#include <cuda_fp16.h>
#include <cstdint>
#include <cstddef>

// Problem constants (fixed by the reference)
#define N_NODES 50000
#define N_EDGES 312500
#define SCAN_BLOCKS 196         // 196 * 256 = 50176 >= N_NODES; co-resident on 148 SMs

// ---------------- scratch (static device globals; no allocation) ----------------
__device__ __align__(16) __half g_x  [(size_t)N_NODES * 256];
__device__ __align__(16) __half g_tx1[(size_t)N_NODES * 256];
__device__ __align__(16) __half g_tx2[(size_t)N_NODES * 256];
__device__ __align__(16) __half g_h  [(size_t)N_NODES * 256];
__device__ __align__(16) __half g_p  [(size_t)N_NODES * 128];
__device__ __align__(16) __half g_w1t[256 * 768];   // W1^T [n][k]
__device__ __align__(16) __half g_w2t[256 * 512];   // fused layer-2 B^T [n][k]
__device__ float g_deg[N_NODES];
__device__ int   g_cnt[N_NODES];
__device__ int   g_fill[N_NODES];
__device__ int   g_rowptr[N_NODES + 1];
__device__ int   g_dst[N_EDGES];
__device__ float g_w[N_EDGES];
__device__ int   g_is64;
__device__ int   g_bsum[256];
__device__ int   g_boff[256];
__device__ int   g_scan_ctr;
__device__ int   g_scan_done;
__device__ int   g_scan_ctr2;
__device__ int   g_scan_done2;

// Buffer ids: 1 = tx1, 2 = tx2, 3 = h, 4 = x, 5 = p.
template <int ID>
__device__ __forceinline__ const __half* hbuf() {
    if (ID == 1) return g_tx1;
    if (ID == 2) return g_tx2;
    if (ID == 3) return g_h;
    if (ID == 4) return g_x;
    return g_p;
}
template <int ID>
__device__ __forceinline__ __half* hbuf_w() {
    if (ID == 1) return g_tx1;
    if (ID == 2) return g_tx2;
    if (ID == 3) return g_h;
    if (ID == 4) return g_x;
    return g_p;
}

// ---------------- cp.async ----------------
__device__ __forceinline__ void cpasync16(uint32_t dst, const void* src, int srcsize) {
    asm volatile("cp.async.ca.shared.global [%0], [%1], 16, %2;\n"
                 :: "r"(dst), "l"(src), "r"(srcsize));
}
__device__ __forceinline__ void cp_commit() {
    asm volatile("cp.async.commit_group;\n" ::: "memory");
}
__device__ __forceinline__ void cp_wait2() {
    asm volatile("cp.async.wait_group 2;\n" ::: "memory");
}
__device__ __forceinline__ void cp_wait1() {
    asm volatile("cp.async.wait_group 1;\n" ::: "memory");
}
__device__ __forceinline__ void cp_wait0() {
    asm volatile("cp.async.wait_group 0;\n" ::: "memory");
}

// ---------------- fp16 mma + ldmatrix ----------------
__device__ __forceinline__ void mma_f16(float c[4], const uint32_t a[4],
                                        const uint32_t b[2]) {
    asm volatile(
        "mma.sync.aligned.m16n8k16.row.col.f32.f16.f16.f32 "
        "{%0,%1,%2,%3}, {%4,%5,%6,%7}, {%8,%9}, {%0,%1,%2,%3};\n"
        : "+f"(c[0]), "+f"(c[1]), "+f"(c[2]), "+f"(c[3])
        : "r"(a[0]), "r"(a[1]), "r"(a[2]), "r"(a[3]), "r"(b[0]), "r"(b[1]));
}

__device__ __forceinline__ void ldsm_x4(uint32_t& r0, uint32_t& r1,
                                        uint32_t& r2, uint32_t& r3,
                                        uint32_t saddr) {
    asm volatile("ldmatrix.sync.aligned.m8n8.x4.shared.b16 {%0,%1,%2,%3}, [%4];"
                 : "=r"(r0), "=r"(r1), "=r"(r2), "=r"(r3) : "r"(saddr));
}

// ---------------- edge-index accessors ----------------
__device__ __forceinline__ int edge_row(const int* ei, int e) {
    return g_is64 ? ei[2 * e] : ei[e];
}
__device__ __forceinline__ int edge_col(const int* ei, int e) {
    return g_is64 ? ei[2 * (N_EDGES + e)] : ei[N_EDGES + e];
}

// ---------------- merged init: zero counters + dtype detect + scan flags ----------------
__global__ void init_kernel(const int* __restrict__ ei) {
    int i = blockIdx.x * 256 + threadIdx.x;
    if (i < N_NODES) {
        g_deg[i] = 0.f;
        g_cnt[i] = 0;
        g_fill[i] = 0;
    }
    if (blockIdx.x == 1 && threadIdx.x == 0) {
        g_scan_ctr = 0;
        g_scan_done = 0;
        g_scan_ctr2 = 0;
        g_scan_done2 = 0;
    }
    if (blockIdx.x == 0) {
        __shared__ int any_nonzero;
        if (threadIdx.x == 0) any_nonzero = 0;
        __syncthreads();
        for (int j = threadIdx.x; j < 2048; j += 256) {
            if (ei[2 * j + 1] != 0) { any_nonzero = 1; break; }
        }
        __syncthreads();
        if (threadIdx.x == 0) g_is64 = (any_nonzero == 0) ? 1 : 0;
    }
}

// ---------------- merged prep: conv_x + deg_count + weight prep ----------------
__global__ void prep_kernel(const int* __restrict__ ei,
                            const float* __restrict__ ew,
                            const float* __restrict__ x,
                            const float* __restrict__ W1,
                            const float* __restrict__ W2) {
    int i = blockIdx.x * 256 + threadIdx.x;

    // Task 1: x -> half (uint2 = 4 halfs each; N_NODES*64 items)
    if (i < N_NODES * 64) {
        float4 v = ((const float4*)x)[i];
        __half2 h0 = __floats2half2_rn(v.x, v.y);
        __half2 h1 = __floats2half2_rn(v.z, v.w);
        uint2 o;
        o.x = *(uint32_t*)&h0;
        o.y = *(uint32_t*)&h1;
        ((uint2*)g_x)[i] = o;
    }
    // Task 2: degree + count
    if (i < N_EDGES) {
        int r = edge_row(ei, i);
        atomicAdd(&g_deg[r], ew[i]);
        atomicAdd(&g_cnt[r], 1);
    }
    // Task 3: weight transpose/fold to half (2x folded into W2_2 for P path)
    if (i < 256 * 768) {
        int n = i / 768, k = i % 768;
        g_w1t[i] = __float2half_rn(W1[k * 256 + n]);
    } else if (i < 256 * 768 + 256 * 512) {
        int j = i - 256 * 768;
        int n = j / 512, k = j % 512;
        float v;
        if (n < 128) {
            v = (k < 256) ? (W2[k * 128 + n] - W2[65536 + k * 128 + n])
                          : W2[32768 + (k - 256) * 128 + n];
        } else {
            v = (k < 256) ? 0.f : 2.f * W2[65536 + (k - 256) * 128 + (n - 128)];
        }
        g_w2t[j] = __float2half_rn(v);
    }
}

// ---------------- fused scan + CSR build (two ticket barriers) ----------------
// Safe: all 196 blocks (256 thr) are co-resident on 148 SMs.
__global__ void scan_build_kernel(const int* __restrict__ ei,
                                  const float* __restrict__ ew) {
    __shared__ int s[256];
    __shared__ int is_last;
    __shared__ int blockoff;
    int t = threadIdx.x;
    int b = blockIdx.x;
    int i = b * 256 + t;
    int v = (i < N_NODES) ? g_cnt[i] : 0;

    // ---- phase 1: local inclusive scan ----
    s[t] = v;
    __syncthreads();
    for (int off = 1; off < 256; off <<= 1) {
        int u = (t >= off) ? s[t - off] : 0;
        __syncthreads();
        s[t] += u;
        __syncthreads();
    }
    int local_incl = s[t];
    int block_sum = s[255];
    __syncthreads();

    if (t == 0) {
        g_bsum[b] = block_sum;
        __threadfence();
        int ticket = atomicAdd(&g_scan_ctr, 1);
        is_last = (ticket == SCAN_BLOCKS - 1) ? 1 : 0;
    }
    __syncthreads();

    if (is_last) {
        int vv = (t < SCAN_BLOCKS) ? atomicAdd(&g_bsum[t], 0) : 0;
        s[t] = vv;
        __syncthreads();
        for (int off = 1; off < 256; off <<= 1) {
            int u = (t >= off) ? s[t - off] : 0;
            __syncthreads();
            s[t] += u;
            __syncthreads();
        }
        if (t < SCAN_BLOCKS) g_boff[t] = s[t] - vv;   // exclusive
        if (t == 255) g_rowptr[N_NODES] = s[255];
        __threadfence();
        if (t == 0) atomicExch(&g_scan_done, 1);
    }

    if (t == 0) {
        while (atomicAdd(&g_scan_done, 0) == 0) { }
        blockoff = atomicAdd(&g_boff[b], 0);
    }
    __syncthreads();
    if (i < N_NODES) g_rowptr[i] = blockoff + local_incl - v;  // exclusive

    // ---- phase 2 barrier: all rowptr entries visible ----
    if (t == 0) {
        __threadfence();
        int ticket = atomicAdd(&g_scan_ctr2, 1);
        if (ticket == SCAN_BLOCKS - 1) atomicExch(&g_scan_done2, 1);
        while (atomicAdd(&g_scan_done2, 0) == 0) { }
    }
    __syncthreads();

    // ---- phase 3: CSR fill (stride loop over edges) ----
    for (int e = b * 256 + t; e < N_EDGES; e += SCAN_BLOCKS * 256) {
        int r = edge_row(ei, e);
        int c = edge_col(ei, e);
        float dr = g_deg[r], dc = g_deg[c];
        float ir = dr > 0.f ? rsqrtf(dr) : 0.f;
        float ic = dc > 0.f ? rsqrtf(dc) : 0.f;
        float w = -ir * ew[e] * ic;
        int pos = atomicAdd(&g_fill[r], 1);
        int idx = g_rowptr[r] + pos;
        g_dst[idx] = c;
        g_w[idx] = w;
    }
}

// ---------------- fp16 SpMM (256-wide, 2-edge unroll; 128-thread blocks) ----------------
__device__ __forceinline__ void acc8(float* a, uint4 u, float w) {
    float2 f;
    f = __half22float2(*(__half2*)&u.x); a[0] += w * f.x; a[1] += w * f.y;
    f = __half22float2(*(__half2*)&u.y); a[2] += w * f.x; a[3] += w * f.y;
    f = __half22float2(*(__half2*)&u.z); a[4] += w * f.x; a[5] += w * f.y;
    f = __half22float2(*(__half2*)&u.w); a[6] += w * f.x; a[7] += w * f.y;
}

template <int SRC, int SUB, int DST>
__global__ __launch_bounds__(128)
void spmm256_kernel(float alpha, float beta) {
    const __half* src = hbuf<SRC>();
    __half*       dst = hbuf_w<DST>();

    int warp = (blockIdx.x * blockDim.x + threadIdx.x) >> 5;
    int lane = threadIdx.x & 31;
    if (warp >= N_NODES) return;
    int s = g_rowptr[warp];
    int e = g_rowptr[warp + 1];

    float aA[8] = {0, 0, 0, 0, 0, 0, 0, 0};
    float aB[8] = {0, 0, 0, 0, 0, 0, 0, 0};

    int i = s;
    for (; i + 2 <= e; i += 2) {
        float w0 = g_w[i], w1 = g_w[i + 1];
        uint4 u0 = ((const uint4*)(src + (size_t)g_dst[i] * 256))[lane];
        uint4 u1 = ((const uint4*)(src + (size_t)g_dst[i + 1] * 256))[lane];
        acc8(aA, u0, w0);
        acc8(aB, u1, w1);
    }
    if (i < e) {
        uint4 u0 = ((const uint4*)(src + (size_t)g_dst[i] * 256))[lane];
        acc8(aA, u0, g_w[i]);
    }
    float a[8];
#pragma unroll
    for (int j = 0; j < 8; j++) a[j] = aA[j] + aB[j];

    if (SUB >= 0) {
        const __half* sub = hbuf<(SUB >= 0 ? SUB : 1)>();
        uint4 su = ((const uint4*)(sub + (size_t)warp * 256))[lane];
        float sv[8];
        float2 f;
        f = __half22float2(*(__half2*)&su.x); sv[0] = f.x; sv[1] = f.y;
        f = __half22float2(*(__half2*)&su.y); sv[2] = f.x; sv[3] = f.y;
        f = __half22float2(*(__half2*)&su.z); sv[4] = f.x; sv[5] = f.y;
        f = __half22float2(*(__half2*)&su.w); sv[6] = f.x; sv[7] = f.y;
#pragma unroll
        for (int j = 0; j < 8; j++) a[j] = alpha * a[j] + beta * sv[j];
    }

    uint4 o;
    __half2 h;
    h = __floats2half2_rn(a[0], a[1]); o.x = *(uint32_t*)&h;
    h = __floats2half2_rn(a[2], a[3]); o.y = *(uint32_t*)&h;
    h = __floats2half2_rn(a[4], a[5]); o.z = *(uint32_t*)&h;
    h = __floats2half2_rn(a[6], a[7]); o.w = *(uint32_t*)&h;
    ((uint4*)(dst + (size_t)warp * 256))[lane] = o;
}

// ---------------- final SpMM: out(f32) += L @ P (2x pre-folded into P) ----------------
__global__ __launch_bounds__(128)
void spmm_out_kernel(float* __restrict__ out) {
    int warp = (blockIdx.x * blockDim.x + threadIdx.x) >> 5;
    int lane = threadIdx.x & 31;
    if (warp >= N_NODES) return;
    int s = g_rowptr[warp];
    int e = g_rowptr[warp + 1];

    float aA[4] = {0, 0, 0, 0};
    float aB[4] = {0, 0, 0, 0};
    int i = s;
    for (; i + 2 <= e; i += 2) {
        float w0 = g_w[i], w1 = g_w[i + 1];
        uint2 u0 = ((const uint2*)(g_p + (size_t)g_dst[i] * 128))[lane];
        uint2 u1 = ((const uint2*)(g_p + (size_t)g_dst[i + 1] * 128))[lane];
        float2 f;
        f = __half22float2(*(__half2*)&u0.x); aA[0] += w0 * f.x; aA[1] += w0 * f.y;
        f = __half22float2(*(__half2*)&u0.y); aA[2] += w0 * f.x; aA[3] += w0 * f.y;
        f = __half22float2(*(__half2*)&u1.x); aB[0] += w1 * f.x; aB[1] += w1 * f.y;
        f = __half22float2(*(__half2*)&u1.y); aB[2] += w1 * f.x; aB[3] += w1 * f.y;
    }
    if (i < e) {
        float w0 = g_w[i];
        uint2 u0 = ((const uint2*)(g_p + (size_t)g_dst[i] * 128))[lane];
        float2 f;
        f = __half22float2(*(__half2*)&u0.x); aA[0] += w0 * f.x; aA[1] += w0 * f.y;
        f = __half22float2(*(__half2*)&u0.y); aA[2] += w0 * f.x; aA[3] += w0 * f.y;
    }
    float4* op = (float4*)(out + (size_t)warp * 128) + lane;
    float4 o = *op;
    o.x += aA[0] + aB[0];
    o.y += aA[1] + aB[1];
    o.z += aA[2] + aB[2];
    o.w += aA[3] + aB[3];
    *op = o;
}

// ---------------- fp16 mma GEMM: 3-stage cp.async pipeline + ldmatrix ----------------
// Block 128(M) x 128(N), 256 threads, 8 warps (4m x 2n), warp tile 32x64,
// BK = 32 halfs, mma.m16n8k16. Dynamic smem: 3 x (A 128x40 + B 128x40) halfs = 60KB.
// LAYER 1: A=[x|tx1|tx2] (K=768), B=g_w1t, out=h (half, bias+relu).
// LAYER 2: A=[h|Z=tx1] (K=512), B=g_w2t, col<128 -> out(f32,+b2),
//          col>=128 -> P (half, weights pre-scaled by 2); those blocks skip
//          stages 0-7 (zero weights for k<256).

#define GEMM_SMEM_BYTES (3 * 2 * 128 * 40 * 2)   // 61440

template <int LAYER>
__global__ __launch_bounds__(256)
void gemm_h(const float* __restrict__ bias, float* __restrict__ ext_out) {
    const int K  = (LAYER == 1) ? 768 : 512;
    const int NS = K / 32;

    extern __shared__ __half dsm[];
    __half* Asm = dsm;                  // 3 bufs x 5120 halfs
    __half* Bsm = dsm + 3 * 5120;       // 3 bufs x 5120 halfs

    const int tid  = threadIdx.x;
    const int lane = tid & 31;
    const int wid  = tid >> 5;
    const int g = lane >> 2;
    const int t = lane & 3;

    const int bm = blockIdx.y * 128;
    const int bn = blockIdx.x * 128;
    const int wm = (wid & 3) * 32;
    const int wn = (wid >> 2) * 64;

    const uint32_t s_as = (uint32_t)__cvta_generic_to_shared(Asm);
    const uint32_t s_bs = (uint32_t)__cvta_generic_to_shared(Bsm);

    // ldmatrix lane addressing
    const int lsub = lane >> 3;
    const int lrow = lane & 7;
    const int a_off0 = (wm + lrow + ((lsub & 1) ? 8 : 0)) * 40 + ((lsub & 2) ? 8 : 0);
    const int b_off0 = (wn + lrow + ((lsub & 2) ? 8 : 0)) * 40 + ((lsub & 1) ? 8 : 0);

    const int s0 = (LAYER == 2 && bn >= 128) ? 8 : 0;

    float acc[2][8][4];
#pragma unroll
    for (int i = 0; i < 2; i++)
#pragma unroll
        for (int j = 0; j < 8; j++)
#pragma unroll
            for (int q = 0; q < 4; q++) acc[i][j][q] = 0.f;

    const int st_row = tid >> 2;        // 0..63 (x2 passes -> 128)
    const int st_c   = (tid & 3) * 8;   // 0,8,16,24

    auto issue = [&](int s) {
        const int buf = s % 3;
        const __half* seg;
        if (LAYER == 1) seg = (s < 8) ? g_x : ((s < 16) ? g_tx1 : g_tx2);
        else            seg = (s < 8) ? g_h : g_tx1;
        const __half* Bt = (LAYER == 1) ? g_w1t : g_w2t;
        const int kb = (s & 7) * 32;
#pragma unroll
        for (int p = 0; p < 2; p++) {
            int row = p * 64 + st_row;
            int rg = bm + row;
            int ok = (rg < N_NODES) ? 16 : 0;
            const __half* src = seg + (size_t)(ok ? rg : 0) * 256 + kb + st_c;
            cpasync16(s_as + (uint32_t)(buf * 5120 + row * 40 + st_c) * 2, src, ok);
        }
#pragma unroll
        for (int p = 0; p < 2; p++) {
            int n = p * 64 + st_row;
            const __half* src = Bt + (size_t)(bn + n) * K + s * 32 + st_c;
            cpasync16(s_bs + (uint32_t)(buf * 5120 + n * 40 + st_c) * 2, src, 16);
        }
        cp_commit();
    };

    issue(s0);
    issue(s0 + 1);
    issue(s0 + 2);

    for (int s = s0; s < NS; s++) {
        if (NS - 1 - s >= 2)      cp_wait2();
        else if (NS - 1 - s == 1) cp_wait1();
        else                      cp_wait0();
        __syncthreads();
        const int buf = s % 3;
        const uint32_t abase = s_as + (uint32_t)(buf * 5120) * 2;
        const uint32_t bbase = s_bs + (uint32_t)(buf * 5120) * 2;
#pragma unroll
        for (int ks = 0; ks < 2; ks++) {
            const int k0 = ks * 16;
            uint32_t a[2][4];
            uint32_t b[8][2];
#pragma unroll
            for (int i = 0; i < 2; i++)
                ldsm_x4(a[i][0], a[i][1], a[i][2], a[i][3],
                        abase + (uint32_t)(a_off0 + i * 16 * 40 + k0) * 2);
#pragma unroll
            for (int jp = 0; jp < 4; jp++)
                ldsm_x4(b[2 * jp][0], b[2 * jp][1], b[2 * jp + 1][0], b[2 * jp + 1][1],
                        bbase + (uint32_t)(b_off0 + jp * 16 * 40 + k0) * 2);
#pragma unroll
            for (int i = 0; i < 2; i++)
#pragma unroll
                for (int j = 0; j < 8; j++)
                    mma_f16(acc[i][j], a[i], b[j]);
        }
        __syncthreads();
        if (s + 3 < NS) issue(s + 3);
    }

    // ---- epilogue ----
#pragma unroll
    for (int i = 0; i < 2; i++) {
        int r0 = bm + wm + 16 * i + g;
        int r1 = r0 + 8;
#pragma unroll
        for (int j = 0; j < 8; j++) {
            int col = bn + wn + 8 * j + 2 * t;
            float v0 = acc[i][j][0], v1 = acc[i][j][1];
            float v2 = acc[i][j][2], v3 = acc[i][j][3];
            if (LAYER == 1) {
                float bb0 = bias[col], bb1 = bias[col + 1];
                v0 = fmaxf(v0 + bb0, 0.f); v1 = fmaxf(v1 + bb1, 0.f);
                v2 = fmaxf(v2 + bb0, 0.f); v3 = fmaxf(v3 + bb1, 0.f);
                __half2 h01 = __floats2half2_rn(v0, v1);
                __half2 h23 = __floats2half2_rn(v2, v3);
                if (r0 < N_NODES) *(uint32_t*)(g_h + (size_t)r0 * 256 + col) = *(uint32_t*)&h01;
                if (r1 < N_NODES) *(uint32_t*)(g_h + (size_t)r1 * 256 + col) = *(uint32_t*)&h23;
            } else {
                if (col < 128) {
                    float bb0 = bias[col], bb1 = bias[col + 1];
                    if (r0 < N_NODES)
                        *(float2*)(ext_out + (size_t)r0 * 128 + col) = make_float2(v0 + bb0, v1 + bb1);
                    if (r1 < N_NODES)
                        *(float2*)(ext_out + (size_t)r1 * 128 + col) = make_float2(v2 + bb0, v3 + bb1);
                } else {
                    int pc = col - 128;
                    __half2 h01 = __floats2half2_rn(v0, v1);
                    __half2 h23 = __floats2half2_rn(v2, v3);
                    if (r0 < N_NODES) *(uint32_t*)(g_p + (size_t)r0 * 128 + pc) = *(uint32_t*)&h01;
                    if (r1 < N_NODES) *(uint32_t*)(g_p + (size_t)r1 * 128 + pc) = *(uint32_t*)&h23;
                }
            }
        }
    }
}

// ---------------- launch ----------------

extern "C" void kernel_launch(void* const* d_in, const int* in_sizes, int n_in,
                              void* d_out, int out_size) {
    const float* x  = (const float*)d_in[0];
    const int*   ei = (const int*)d_in[1];
    const float* ew = (const float*)d_in[2];
    const float* W1 = (const float*)d_in[3];   // [3,256,256]
    const float* b1 = (const float*)d_in[4];
    const float* W2 = (const float*)d_in[5];   // [3,256,128]
    const float* b2 = (const float*)d_in[6];
    float*       out = (float*)d_out;

    // dynamic smem opt-in (host-side attribute set; idempotent)
    cudaFuncSetAttribute(gemm_h<1>, cudaFuncAttributeMaxDynamicSharedMemorySize, GEMM_SMEM_BYTES);
    cudaFuncSetAttribute(gemm_h<2>, cudaFuncAttributeMaxDynamicSharedMemorySize, GEMM_SMEM_BYTES);

    // CSR build + conversions (3 prelude launches)
    init_kernel<<<SCAN_BLOCKS, 256>>>(ei);
    prep_kernel<<<(N_NODES * 64 + 255) / 256, 256>>>(ei, ew, x, W1, W2);
    scan_build_kernel<<<SCAN_BLOCKS, 256>>>(ei, ew);

    const int spmm_blocks = (N_NODES * 32 + 127) / 128;   // 128-thread blocks
    const dim3 ggrid(2, (N_NODES + 127) / 128);           // N=256 for both layers

    // ---- layer 1 ----
    spmm256_kernel<4, -1, 1><<<spmm_blocks, 128>>>(1.f, 0.f);        // tx1 = L @ x
    spmm256_kernel<1, 4, 2><<<spmm_blocks, 128>>>(2.f, -1.f);        // tx2 = 2 L tx1 - x
    gemm_h<1><<<ggrid, 256, GEMM_SMEM_BYTES>>>(b1, nullptr);         // h

    // ---- layer 2 (commuted + fused) ----
    spmm256_kernel<3, -1, 1><<<spmm_blocks, 128>>>(1.f, 0.f);        // Z = L @ h -> tx1
    gemm_h<2><<<ggrid, 256, GEMM_SMEM_BYTES>>>(b2, out);             // [out_partial | P]
    spmm_out_kernel<<<spmm_blocks, 128>>>(out);                      // out += L @ P

    (void)in_sizes; (void)n_in; (void)out_size;
}